// round 2
// baseline (speedup 1.0000x reference)
#include <cuda_runtime.h>
#include <math.h>

#define NS 256       // sequence length S
#define NB 64        // batch B
#define NE 300       // embedding dim E
#define NH2 256      // hidden per direction
#define NG 1024      // 4*NH2 gates
#define NM 16384     // S*B flattened rows
#define NT 10        // tags
#define IDX_START 8
#define IDX_STOP 9

// ------------------- scratch (static device allocations) -------------------
__device__ float g_G[2][NM][NG];       // precomputed x@wih^T + bih + bhh  (134 MB)
__device__ float g_whhT[2][NH2][NG];   // transposed recurrent weights    (2 MB)
__device__ float g_lstm[NM][2 * NH2];  // concat hidden states            (33.5 MB)
__device__ float g_feats[NM][NT];      // emission scores                 (0.66 MB)

__device__ __forceinline__ float sigf(float x) { return 1.0f / (1.0f + expf(-x)); }

// ------------------- transpose whh (1024x256 -> 256x1024), both dirs -------
__global__ void k_transpose(const float* __restrict__ whh_f,
                            const float* __restrict__ whh_b) {
    __shared__ float tile[32][33];
    const int dir = blockIdx.z;
    const float* src = dir ? whh_b : whh_f;
    const int k0 = blockIdx.x * 32;   // column of whh (0..255)
    const int j0 = blockIdx.y * 32;   // row of whh    (0..1023)
    const int tx = threadIdx.x, ty = threadIdx.y;  // (32, 8)
    #pragma unroll
    for (int i = ty; i < 32; i += 8)
        tile[i][tx] = src[(size_t)(j0 + i) * NH2 + k0 + tx];
    __syncthreads();
    #pragma unroll
    for (int i = ty; i < 32; i += 8)
        g_whhT[dir][k0 + i][j0 + tx] = tile[tx][i];
}

// ------------------- input projection GEMM --------------------------------
// C[t][j] = sum_e emb[tok[t]][e] * wih[j][e]  + (bih[j]+bhh[j])
// M=16384 (gathered rows), N=1024, K=300.  Tile 128x128, 256 threads, 8x8/thread.
__global__ __launch_bounds__(256) void k_input_gemm(
    const int* __restrict__ tok, const float* __restrict__ emb,
    const float* __restrict__ wih, const float* __restrict__ bih,
    const float* __restrict__ bhh, int dir) {
    __shared__ float As[8][128];
    __shared__ float Bs[8][128];
    __shared__ int stok[128];

    const int t0 = blockIdx.x * 128;
    const int j0 = blockIdx.y * 128;
    const int tid = threadIdx.x;
    if (tid < 128) stok[tid] = tok[t0 + tid];
    __syncthreads();

    const int tx = tid & 15;        // 0..15  -> 8 output cols each
    const int ty = tid >> 4;        // 0..15  -> 8 output rows each
    const int r = tid >> 1;         // 0..127 row for loads
    const int q = tid & 1;          // which half (4 floats) of the 8-wide K chunk

    float acc[8][8];
    #pragma unroll
    for (int i = 0; i < 8; ++i)
        #pragma unroll
        for (int j = 0; j < 8; ++j) acc[i][j] = 0.0f;

    for (int k0 = 0; k0 < NE; k0 += 8) {
        const int kc = k0 + q * 4;
        float4 av = make_float4(0.f, 0.f, 0.f, 0.f);
        float4 bv = make_float4(0.f, 0.f, 0.f, 0.f);
        if (kc < NE) {  // NE % 4 == 0 so a guarded float4 never straddles the edge
            av = *(const float4*)(emb + (size_t)stok[r] * NE + kc);
            bv = *(const float4*)(wih + (size_t)(j0 + r) * NE + kc);
        }
        __syncthreads();  // previous tile fully consumed
        As[q * 4 + 0][r] = av.x; As[q * 4 + 1][r] = av.y;
        As[q * 4 + 2][r] = av.z; As[q * 4 + 3][r] = av.w;
        Bs[q * 4 + 0][r] = bv.x; Bs[q * 4 + 1][r] = bv.y;
        Bs[q * 4 + 2][r] = bv.z; Bs[q * 4 + 3][r] = bv.w;
        __syncthreads();
        #pragma unroll
        for (int kk = 0; kk < 8; ++kk) {
            float a[8], b[8];
            *(float4*)&a[0] = *(const float4*)&As[kk][ty * 8];
            *(float4*)&a[4] = *(const float4*)&As[kk][ty * 8 + 4];
            *(float4*)&b[0] = *(const float4*)&Bs[kk][tx * 8];
            *(float4*)&b[4] = *(const float4*)&Bs[kk][tx * 8 + 4];
            #pragma unroll
            for (int i = 0; i < 8; ++i)
                #pragma unroll
                for (int j = 0; j < 8; ++j)
                    acc[i][j] = fmaf(a[i], b[j], acc[i][j]);
        }
    }

    const int jj = j0 + tx * 8;
    float bsum[8];
    #pragma unroll
    for (int j = 0; j < 8; ++j) bsum[j] = bih[jj + j] + bhh[jj + j];
    #pragma unroll
    for (int i = 0; i < 8; ++i) {
        float* dst = &g_G[dir][t0 + ty * 8 + i][jj];
        #pragma unroll
        for (int j = 0; j < 8; ++j) dst[j] = acc[i][j] + bsum[j];
    }
}

// ------------------- recurrent LSTM ----------------------------------------
// 32 CTAs: blk>>4 = dir, (blk&15)*4 = 4 batch lanes per CTA. 256 threads.
// Per step: gates = G_row + whhT^T h ; thread tid owns gate quad j=4*tid..+3
// for matvec, then hidden unit u=tid for the nonlinearity/update.
__global__ __launch_bounds__(256) void k_lstm(const float* __restrict__ h0,
                                              const float* __restrict__ c0) {
    const int blk = blockIdx.x;
    const int dir = blk >> 4;
    const int bg0 = (blk & 15) * 4;
    const int tid = threadIdx.x;

    __shared__ float4 hs[NH2];       // h[k] packed over 4 batch lanes
    __shared__ float gbuf[4][NG];    // gates per batch lane

    const float4* __restrict__ W = (const float4*)&g_whhT[dir][0][0];
    const float* __restrict__ Gd = &g_G[dir][0][0];

    float4 c;
    {
        const int base = (dir * NB + bg0) * NH2 + tid;
        c.x = c0[base];           c.y = c0[base + NH2];
        c.z = c0[base + 2 * NH2]; c.w = c0[base + 3 * NH2];
        float4 h;
        h.x = h0[base];           h.y = h0[base + NH2];
        h.z = h0[base + 2 * NH2]; h.w = h0[base + 3 * NH2];
        hs[tid] = h;
    }
    __syncthreads();

    for (int si = 0; si < NS; ++si) {
        const int s = dir ? (NS - 1 - si) : si;

        // issue the (DRAM-resident) input-gate loads early; consumed after matvec
        const float* Gr = Gd + ((size_t)(s * NB + bg0)) * NG + 4 * tid;
        const float4 gin0 = *(const float4*)(Gr);
        const float4 gin1 = *(const float4*)(Gr + NG);
        const float4 gin2 = *(const float4*)(Gr + 2 * NG);
        const float4 gin3 = *(const float4*)(Gr + 3 * NG);

        float4 a0 = make_float4(0.f, 0.f, 0.f, 0.f);
        float4 a1 = a0, a2 = a0, a3 = a0;
        #pragma unroll 4
        for (int k = 0; k < NH2; ++k) {
            const float4 w = W[(k << 8) + tid];   // coalesced, L2-resident
            const float4 hk = hs[k];              // broadcast
            a0.x = fmaf(w.x, hk.x, a0.x); a0.y = fmaf(w.y, hk.x, a0.y);
            a0.z = fmaf(w.z, hk.x, a0.z); a0.w = fmaf(w.w, hk.x, a0.w);
            a1.x = fmaf(w.x, hk.y, a1.x); a1.y = fmaf(w.y, hk.y, a1.y);
            a1.z = fmaf(w.z, hk.y, a1.z); a1.w = fmaf(w.w, hk.y, a1.w);
            a2.x = fmaf(w.x, hk.z, a2.x); a2.y = fmaf(w.y, hk.z, a2.y);
            a2.z = fmaf(w.z, hk.z, a2.z); a2.w = fmaf(w.w, hk.z, a2.w);
            a3.x = fmaf(w.x, hk.w, a3.x); a3.y = fmaf(w.y, hk.w, a3.y);
            a3.z = fmaf(w.z, hk.w, a3.z); a3.w = fmaf(w.w, hk.w, a3.w);
        }
        a0.x += gin0.x; a0.y += gin0.y; a0.z += gin0.z; a0.w += gin0.w;
        a1.x += gin1.x; a1.y += gin1.y; a1.z += gin1.z; a1.w += gin1.w;
        a2.x += gin2.x; a2.y += gin2.y; a2.z += gin2.z; a2.w += gin2.w;
        a3.x += gin3.x; a3.y += gin3.y; a3.z += gin3.z; a3.w += gin3.w;

        *(float4*)&gbuf[0][4 * tid] = a0;
        *(float4*)&gbuf[1][4 * tid] = a1;
        *(float4*)&gbuf[2][4 * tid] = a2;
        *(float4*)&gbuf[3][4 * tid] = a3;
        __syncthreads();   // gates visible; matvec reads of hs done -> safe to overwrite

        float4 nh;
        {
            float ig, fg, gg, og, cc;
            ig = sigf(gbuf[0][tid]);       fg = sigf(gbuf[0][tid + 256]);
            gg = tanhf(gbuf[0][tid + 512]); og = sigf(gbuf[0][tid + 768]);
            cc = fg * c.x + ig * gg; c.x = cc; nh.x = og * tanhf(cc);

            ig = sigf(gbuf[1][tid]);       fg = sigf(gbuf[1][tid + 256]);
            gg = tanhf(gbuf[1][tid + 512]); og = sigf(gbuf[1][tid + 768]);
            cc = fg * c.y + ig * gg; c.y = cc; nh.y = og * tanhf(cc);

            ig = sigf(gbuf[2][tid]);       fg = sigf(gbuf[2][tid + 256]);
            gg = tanhf(gbuf[2][tid + 512]); og = sigf(gbuf[2][tid + 768]);
            cc = fg * c.z + ig * gg; c.z = cc; nh.z = og * tanhf(cc);

            ig = sigf(gbuf[3][tid]);       fg = sigf(gbuf[3][tid + 256]);
            gg = tanhf(gbuf[3][tid + 512]); og = sigf(gbuf[3][tid + 768]);
            cc = fg * c.w + ig * gg; c.w = cc; nh.w = og * tanhf(cc);
        }
        hs[tid] = nh;
        float* lrow = &g_lstm[s * NB + bg0][dir * NH2 + tid];
        lrow[0] = nh.x; lrow[512] = nh.y; lrow[1024] = nh.z; lrow[1536] = nh.w;
        __syncthreads();   // hs ready for next step
    }
}

// ------------------- emission features: lstm_out @ W_out^T + b_out ---------
__global__ __launch_bounds__(256) void k_feats(const float* __restrict__ Wout,
                                               const float* __restrict__ bout) {
    __shared__ float sW[NT][2 * NH2];  // 20 KB
    const int tid = threadIdx.x;
    for (int i = tid; i < NT * 2 * NH2; i += 256) sW[i / (2 * NH2)][i % (2 * NH2)] = Wout[i];
    __syncthreads();

    const int warp = tid >> 5, lane = tid & 31;
    const int n = blockIdx.x * 8 + warp;
    const float4* row = (const float4*)&g_lstm[n][0];  // 128 float4s

    float p[NT];
    #pragma unroll
    for (int t = 0; t < NT; ++t) p[t] = 0.0f;
    for (int q = lane; q < 128; q += 32) {
        const float4 v = row[q];
        #pragma unroll
        for (int t = 0; t < NT; ++t) {
            const float4 w = ((const float4*)&sW[t][0])[q];
            p[t] += v.x * w.x + v.y * w.y + v.z * w.z + v.w * w.w;
        }
    }
    #pragma unroll
    for (int off = 16; off; off >>= 1)
        #pragma unroll
        for (int t = 0; t < NT; ++t)
            p[t] += __shfl_down_sync(0xffffffffu, p[t], off);
    if (lane == 0) {
        #pragma unroll
        for (int t = 0; t < NT; ++t) g_feats[n][t] = p[t] + bout[t];
    }
}

// ------------------- Viterbi decode (1 warp per batch element) -------------
__global__ void k_viterbi(const float* __restrict__ trans, float* __restrict__ out) {
    const int b = blockIdx.x;
    const int lane = threadIdx.x;  // 32 threads
    __shared__ float st[NT * NT];
    __shared__ unsigned char bp[NS][NT];
    for (int i = lane; i < NT * NT; i += 32) st[i] = trans[i];
    __syncwarp();

    float fv = (lane == IDX_START) ? 0.0f : -10000.0f;
    for (int s = 0; s < NS; ++s) {
        float best = -3.4e38f;
        int barg = 0;
        const float cur = fv;
        #pragma unroll
        for (int p = 0; p < NT; ++p) {
            const float fp = __shfl_sync(0xffffffffu, cur, p);
            if (lane < NT) {
                const float v = fp + st[lane * NT + p];
                if (v > best) { best = v; barg = p; }  // first-max like argmax
            }
        }
        float feat = 0.0f;
        if (lane < NT) feat = g_feats[b * NS + s][lane];
        fv = best + feat;
        if (lane < NT) bp[s][lane] = (unsigned char)barg;
        __syncwarp();
    }
    float m = (lane < NT) ? (fv + st[IDX_STOP * NT + lane]) : -3.4e38f;
    int mi = lane;
    #pragma unroll
    for (int off = 16; off; off >>= 1) {
        const float om = __shfl_down_sync(0xffffffffu, m, off);
        const int oi = __shfl_down_sync(0xffffffffu, mi, off);
        if (om > m || (om == m && oi < mi)) { m = om; mi = oi; }
    }
    if (lane == 0) {
        out[b] = m;  // path_score
        int best = mi;
        for (int s = NS - 1; s >= 0; --s) {
            out[NB + b * NS + s] = (float)best;
            best = bp[s][best];
        }
    }
}

// ------------------- launcher ----------------------------------------------
extern "C" void kernel_launch(void* const* d_in, const int* in_sizes, int n_in,
                              void* d_out, int out_size) {
    const int*   sent  = (const int*)d_in[0];
    const float* emb   = (const float*)d_in[1];
    const float* wih_f = (const float*)d_in[2];
    const float* whh_f = (const float*)d_in[3];
    const float* bih_f = (const float*)d_in[4];
    const float* bhh_f = (const float*)d_in[5];
    const float* wih_b = (const float*)d_in[6];
    const float* whh_b = (const float*)d_in[7];
    const float* bih_b = (const float*)d_in[8];
    const float* bhh_b = (const float*)d_in[9];
    const float* Wout  = (const float*)d_in[10];
    const float* bout  = (const float*)d_in[11];

    // transitions is the unique size-100 input; order of the last 3 varies
    const float *trans, *h0, *c0;
    if (n_in > 12 && in_sizes[12] == NT * NT) {
        trans = (const float*)d_in[12];
        h0    = (const float*)d_in[13];
        c0    = (const float*)d_in[14];
    } else {
        h0    = (const float*)d_in[12];
        c0    = (const float*)d_in[13];
        trans = (const float*)d_in[14];
    }

    {
        dim3 tg(8, 32, 2), tb(32, 8);
        k_transpose<<<tg, tb>>>(whh_f, whh_b);
    }
    {
        dim3 gg(NM / 128, NG / 128);
        k_input_gemm<<<gg, 256>>>(sent, emb, wih_f, bih_f, bhh_f, 0);
        k_input_gemm<<<gg, 256>>>(sent, emb, wih_b, bih_b, bhh_b, 1);
    }
    k_lstm<<<32, 256>>>(h0, c0);
    k_feats<<<NM / 8, 256>>>(Wout, bout);
    k_viterbi<<<NB, 32>>>(trans, (float*)d_out);
}

// round 3
// speedup vs baseline: 3.1193x; 3.1193x over previous
#include <cuda_runtime.h>
#include <math.h>

#define NS 256       // sequence length S
#define NB 64        // batch B
#define NE 300       // embedding dim E
#define NH2 256      // hidden per direction
#define NG 1024      // 4*NH2 gates
#define NM 16384     // S*B flattened rows
#define NT 10        // tags
#define IDX_START 8
#define IDX_STOP 9

// LSTM cluster geometry
#define CLS 8        // CTAs per cluster
#define LANES 8      // batch lanes per cluster
#define UPC 32       // hidden units per CTA (NH2 / CLS)
#define ROWS 128     // gate rows per CTA (4 * UPC)
#define SW_PITCH 260 // padded weight row (conflict-free LDS.128)
#define GB_PITCH 12  // padded gate buffer row

// dynamic smem layout (floats)
#define SW_OFF 0
#define HB_OFF (ROWS * SW_PITCH)              // 33280
#define GB_OFF (HB_OFF + 2 * NH2 * LANES)     // +4096
#define DSM_FLOATS (GB_OFF + ROWS * GB_PITCH) // +1536 = 38912 floats (152 KB)

// ------------------- scratch (static device allocations) -------------------
__device__ float g_G[2][NM][NG];       // precomputed x@wih^T + bih + bhh  (134 MB)
__device__ float g_lstm[NM][2 * NH2];  // concat hidden states            (33.5 MB)
__device__ float g_feats[NM][NT];      // emission scores                 (0.66 MB)

__device__ __forceinline__ float sigf(float x) { return 1.0f / (1.0f + expf(-x)); }

__device__ __forceinline__ unsigned smem_u32(const void* p) {
    unsigned a;
    asm("{ .reg .u64 t; cvta.to.shared.u64 t, %1; cvt.u32.u64 %0, t; }" : "=r"(a) : "l"(p));
    return a;
}
__device__ __forceinline__ unsigned ctarank() {
    unsigned r; asm("mov.u32 %0, %%cluster_ctarank;" : "=r"(r)); return r;
}

// ------------------- input projection GEMM --------------------------------
// C[t][j] = sum_e emb[tok[t]][e] * wih[j][e]  + (bih[j]+bhh[j])
// M=16384 (gathered rows), N=1024, K=300.  Tile 128x128, 256 threads, 8x8/thread.
__global__ __launch_bounds__(256) void k_input_gemm(
    const int* __restrict__ tok, const float* __restrict__ emb,
    const float* __restrict__ wih, const float* __restrict__ bih,
    const float* __restrict__ bhh, int dir) {
    __shared__ float As[8][128];
    __shared__ float Bs[8][128];
    __shared__ int stok[128];

    const int t0 = blockIdx.x * 128;
    const int j0 = blockIdx.y * 128;
    const int tid = threadIdx.x;
    if (tid < 128) stok[tid] = tok[t0 + tid];
    __syncthreads();

    const int tx = tid & 15;
    const int ty = tid >> 4;
    const int r = tid >> 1;
    const int q = tid & 1;

    float acc[8][8];
    #pragma unroll
    for (int i = 0; i < 8; ++i)
        #pragma unroll
        for (int j = 0; j < 8; ++j) acc[i][j] = 0.0f;

    for (int k0 = 0; k0 < NE; k0 += 8) {
        const int kc = k0 + q * 4;
        float4 av = make_float4(0.f, 0.f, 0.f, 0.f);
        float4 bv = make_float4(0.f, 0.f, 0.f, 0.f);
        if (kc < NE) {
            av = *(const float4*)(emb + (size_t)stok[r] * NE + kc);
            bv = *(const float4*)(wih + (size_t)(j0 + r) * NE + kc);
        }
        __syncthreads();
        As[q * 4 + 0][r] = av.x; As[q * 4 + 1][r] = av.y;
        As[q * 4 + 2][r] = av.z; As[q * 4 + 3][r] = av.w;
        Bs[q * 4 + 0][r] = bv.x; Bs[q * 4 + 1][r] = bv.y;
        Bs[q * 4 + 2][r] = bv.z; Bs[q * 4 + 3][r] = bv.w;
        __syncthreads();
        #pragma unroll
        for (int kk = 0; kk < 8; ++kk) {
            float a[8], b[8];
            *(float4*)&a[0] = *(const float4*)&As[kk][ty * 8];
            *(float4*)&a[4] = *(const float4*)&As[kk][ty * 8 + 4];
            *(float4*)&b[0] = *(const float4*)&Bs[kk][tx * 8];
            *(float4*)&b[4] = *(const float4*)&Bs[kk][tx * 8 + 4];
            #pragma unroll
            for (int i = 0; i < 8; ++i)
                #pragma unroll
                for (int j = 0; j < 8; ++j)
                    acc[i][j] = fmaf(a[i], b[j], acc[i][j]);
        }
    }

    const int jj = j0 + tx * 8;
    float bsum[8];
    #pragma unroll
    for (int j = 0; j < 8; ++j) bsum[j] = bih[jj + j] + bhh[jj + j];
    #pragma unroll
    for (int i = 0; i < 8; ++i) {
        float* dst = &g_G[dir][t0 + ty * 8 + i][jj];
        #pragma unroll
        for (int j = 0; j < 8; ++j) dst[j] = acc[i][j] + bsum[j];
    }
}

// ------------------- clustered recurrent LSTM ------------------------------
// 128 CTAs = 16 clusters of 8. Cluster cid: dir = cid>>3, lanes (cid&7)*8..+8.
// CTA rank owns 32 hidden units (128 gate rows), whh slice resident in SMEM.
// h (256 units x 8 lanes) is replicated in every CTA's SMEM, double-buffered;
// each CTA broadcasts its 32 new h-units to all peers via st.shared::cluster,
// then one cluster barrier per step provides ordering (release/acquire).
__global__ __launch_bounds__(256, 1) __cluster_dims__(CLS, 1, 1)
void k_lstm(const float* __restrict__ whh_f, const float* __restrict__ whh_b,
            const float* __restrict__ h0, const float* __restrict__ c0) {
    extern __shared__ float dsm[];
    const int tid = threadIdx.x;
    const unsigned rank = ctarank();
    const int cid = blockIdx.x >> 3;
    const int dir = cid >> 3;
    const int bg0 = (cid & 7) * LANES;
    const int u0 = rank * UPC;

    const float* __restrict__ whh = dir ? whh_b : whh_f;

    // ---- load weight slice into smem (rows ordered i,f,g,o per unit block)
    for (int idx = tid; idx < ROWS * NH2; idx += 256) {
        const int row = idx >> 8, k = idx & 255;
        const int grow = ((row >> 5) << 8) + u0 + (row & 31);  // global gate row
        dsm[SW_OFF + row * SW_PITCH + k] = whh[(size_t)grow * NH2 + k];
    }
    // ---- init h buffer 0 (full 256 x 8 lanes)
    for (int j = tid; j < NH2 * LANES; j += 256) {
        const int k = j >> 3, l = j & 7;
        dsm[HB_OFF + k * 8 + l] = h0[(size_t)(dir * NB + bg0 + l) * NH2 + k];
    }
    // ---- epilogue thread state: c for (unit u0+u, lane l)
    const int eu = tid >> 3, el = tid & 7;   // u in [0,32), l in [0,8)
    float c = c0[(size_t)(dir * NB + bg0 + el) * NH2 + u0 + eu];

    // ---- precompute peer hbuf base addresses via mapa
    const unsigned hb_local = smem_u32(&dsm[HB_OFF]);
    unsigned hb_peer[CLS];
    #pragma unroll
    for (int j = 0; j < CLS; ++j) {
        asm("mapa.shared::cluster.u32 %0, %1, %2;"
            : "=r"(hb_peer[j]) : "r"(hb_local), "r"(j));
    }

    __syncthreads();
    asm volatile("barrier.cluster.arrive.aligned;" ::: "memory");
    asm volatile("barrier.cluster.wait.aligned;" ::: "memory");

    // matvec thread mapping: row r in [0,128), lane group lg in {0,4}
    const int r = tid & 127;
    const int lg = (tid >> 7) << 2;
    const int gidx = ((r >> 5) << 8) + u0 + (r & 31);   // global gate index
    const float* __restrict__ Wr = &dsm[SW_OFF + r * SW_PITCH];
    const float* __restrict__ Gd = &g_G[dir][0][0];

    int p = 0;
    for (int si = 0; si < NS; ++si) {
        const int s = dir ? (NS - 1 - si) : si;

        // phase A: prefetch input-gate contributions (DRAM/L2, hidden by matvec)
        const float* Gp = Gd + (size_t)(s * NB + bg0 + lg) * NG + gidx;
        const float gin0 = Gp[0];
        const float gin1 = Gp[NG];
        const float gin2 = Gp[2 * NG];
        const float gin3 = Gp[3 * NG];

        // phase B: matvec  a[j] = sum_k W[r][k] * h[k][lg+j]
        const float* __restrict__ Hb = &dsm[HB_OFF + p * (NH2 * LANES)];
        float a0 = 0.f, a1 = 0.f, a2 = 0.f, a3 = 0.f;
        #pragma unroll 8
        for (int kk = 0; kk < NH2; kk += 4) {
            const float4 w  = *(const float4*)(Wr + kk);
            const float4 hA = *(const float4*)(Hb + (kk + 0) * 8 + lg);
            const float4 hB = *(const float4*)(Hb + (kk + 1) * 8 + lg);
            const float4 hC = *(const float4*)(Hb + (kk + 2) * 8 + lg);
            const float4 hD = *(const float4*)(Hb + (kk + 3) * 8 + lg);
            a0 = fmaf(w.x, hA.x, a0); a1 = fmaf(w.x, hA.y, a1);
            a2 = fmaf(w.x, hA.z, a2); a3 = fmaf(w.x, hA.w, a3);
            a0 = fmaf(w.y, hB.x, a0); a1 = fmaf(w.y, hB.y, a1);
            a2 = fmaf(w.y, hB.z, a2); a3 = fmaf(w.y, hB.w, a3);
            a0 = fmaf(w.z, hC.x, a0); a1 = fmaf(w.z, hC.y, a1);
            a2 = fmaf(w.z, hC.z, a2); a3 = fmaf(w.z, hC.w, a3);
            a0 = fmaf(w.w, hD.x, a0); a1 = fmaf(w.w, hD.y, a1);
            a2 = fmaf(w.w, hD.z, a2); a3 = fmaf(w.w, hD.w, a3);
        }

        // phase C: add input gates, stage to gbuf
        *(float4*)&dsm[GB_OFF + r * GB_PITCH + lg] =
            make_float4(a0 + gin0, a1 + gin1, a2 + gin2, a3 + gin3);
        __syncthreads();

        // phase D: LSTM cell for (unit eu, lane el)
        {
            const float gi = dsm[GB_OFF + (eu)        * GB_PITCH + el];
            const float gf = dsm[GB_OFF + (32 + eu)   * GB_PITCH + el];
            const float gg = dsm[GB_OFF + (64 + eu)   * GB_PITCH + el];
            const float go = dsm[GB_OFF + (96 + eu)   * GB_PITCH + el];
            const float iv = sigf(gi), fv = sigf(gf), gv = tanhf(gg), ov = sigf(go);
            c = fv * c + iv * gv;
            const float h = ov * tanhf(c);

            // broadcast new h to all 8 CTAs (incl. self), buffer p^1
            const unsigned off = (((p ^ 1) * (NH2 * LANES)) + (u0 + eu) * 8 + el) * 4u;
            #pragma unroll
            for (int j = 0; j < CLS; ++j)
                asm volatile("st.shared::cluster.f32 [%0], %1;"
                             :: "r"(hb_peer[j] + off), "f"(h) : "memory");

            g_lstm[s * NB + bg0 + el][dir * NH2 + u0 + eu] = h;
        }

        // phase E: cluster barrier (release peer stores / acquire for next read)
        asm volatile("barrier.cluster.arrive.aligned;" ::: "memory");
        asm volatile("barrier.cluster.wait.aligned;" ::: "memory");
        p ^= 1;
    }
}

// ------------------- emission features: lstm_out @ W_out^T + b_out ---------
__global__ __launch_bounds__(256) void k_feats(const float* __restrict__ Wout,
                                               const float* __restrict__ bout) {
    __shared__ float sW[NT][2 * NH2];
    const int tid = threadIdx.x;
    for (int i = tid; i < NT * 2 * NH2; i += 256) sW[i / (2 * NH2)][i % (2 * NH2)] = Wout[i];
    __syncthreads();

    const int warp = tid >> 5, lane = tid & 31;
    const int n = blockIdx.x * 8 + warp;
    const float4* row = (const float4*)&g_lstm[n][0];

    float pAcc[NT];
    #pragma unroll
    for (int t = 0; t < NT; ++t) pAcc[t] = 0.0f;
    for (int q = lane; q < 128; q += 32) {
        const float4 v = row[q];
        #pragma unroll
        for (int t = 0; t < NT; ++t) {
            const float4 w = ((const float4*)&sW[t][0])[q];
            pAcc[t] += v.x * w.x + v.y * w.y + v.z * w.z + v.w * w.w;
        }
    }
    #pragma unroll
    for (int off = 16; off; off >>= 1)
        #pragma unroll
        for (int t = 0; t < NT; ++t)
            pAcc[t] += __shfl_down_sync(0xffffffffu, pAcc[t], off);
    if (lane == 0) {
        #pragma unroll
        for (int t = 0; t < NT; ++t) g_feats[n][t] = pAcc[t] + bout[t];
    }
}

// ------------------- Viterbi decode (1 warp per batch element) -------------
__global__ void k_viterbi(const float* __restrict__ trans, float* __restrict__ out) {
    const int b = blockIdx.x;
    const int lane = threadIdx.x;
    __shared__ float st[NT * NT];
    __shared__ unsigned char bp[NS][NT];
    for (int i = lane; i < NT * NT; i += 32) st[i] = trans[i];
    __syncwarp();

    float fv = (lane == IDX_START) ? 0.0f : -10000.0f;
    for (int s = 0; s < NS; ++s) {
        float best = -3.4e38f;
        int barg = 0;
        const float cur = fv;
        #pragma unroll
        for (int p = 0; p < NT; ++p) {
            const float fp = __shfl_sync(0xffffffffu, cur, p);
            if (lane < NT) {
                const float v = fp + st[lane * NT + p];
                if (v > best) { best = v; barg = p; }
            }
        }
        float feat = 0.0f;
        if (lane < NT) feat = g_feats[b * NS + s][lane];
        fv = best + feat;
        if (lane < NT) bp[s][lane] = (unsigned char)barg;
        __syncwarp();
    }
    float m = (lane < NT) ? (fv + st[IDX_STOP * NT + lane]) : -3.4e38f;
    int mi = lane;
    #pragma unroll
    for (int off = 16; off; off >>= 1) {
        const float om = __shfl_down_sync(0xffffffffu, m, off);
        const int oi = __shfl_down_sync(0xffffffffu, mi, off);
        if (om > m || (om == m && oi < mi)) { m = om; mi = oi; }
    }
    if (lane == 0) {
        out[b] = m;
        int best = mi;
        for (int s = NS - 1; s >= 0; --s) {
            out[NB + b * NS + s] = (float)best;
            best = bp[s][best];
        }
    }
}

// ------------------- launcher ----------------------------------------------
extern "C" void kernel_launch(void* const* d_in, const int* in_sizes, int n_in,
                              void* d_out, int out_size) {
    const int*   sent  = (const int*)d_in[0];
    const float* emb   = (const float*)d_in[1];
    const float* wih_f = (const float*)d_in[2];
    const float* whh_f = (const float*)d_in[3];
    const float* bih_f = (const float*)d_in[4];
    const float* bhh_f = (const float*)d_in[5];
    const float* wih_b = (const float*)d_in[6];
    const float* whh_b = (const float*)d_in[7];
    const float* bih_b = (const float*)d_in[8];
    const float* bhh_b = (const float*)d_in[9];
    const float* Wout  = (const float*)d_in[10];
    const float* bout  = (const float*)d_in[11];

    const float *trans, *h0, *c0;
    if (n_in > 12 && in_sizes[12] == NT * NT) {
        trans = (const float*)d_in[12];
        h0    = (const float*)d_in[13];
        c0    = (const float*)d_in[14];
    } else {
        h0    = (const float*)d_in[12];
        c0    = (const float*)d_in[13];
        trans = (const float*)d_in[14];
    }

    static int smem_set = 0;
    const int lstm_smem = DSM_FLOATS * (int)sizeof(float);  // ~152 KB
    if (!smem_set) {
        cudaFuncSetAttribute(k_lstm, cudaFuncAttributeMaxDynamicSharedMemorySize,
                             lstm_smem);
        smem_set = 1;
    }

    {
        dim3 gg(NM / 128, NG / 128);
        k_input_gemm<<<gg, 256>>>(sent, emb, wih_f, bih_f, bhh_f, 0);
        k_input_gemm<<<gg, 256>>>(sent, emb, wih_b, bih_b, bhh_b, 1);
    }
    k_lstm<<<128, 256, lstm_smem>>>(whh_f, whh_b, h0, c0);
    k_feats<<<NM / 8, 256>>>(Wout, bout);
    k_viterbi<<<NB, 32>>>(trans, (float*)d_out);
}

// round 4
// speedup vs baseline: 3.4053x; 1.0917x over previous
#include <cuda_runtime.h>
#include <math.h>

#define NS 256       // sequence length S
#define NB 64        // batch B
#define NE 300       // embedding dim E
#define NH2 256      // hidden per direction
#define NG 1024      // 4*NH2 gates
#define NM 16384     // S*B flattened rows
#define NT 10        // tags
#define IDX_START 8
#define IDX_STOP 9

// LSTM cluster geometry
#define CLS 8        // CTAs per cluster
#define LANES 8      // batch lanes per cluster
#define UPC 32       // hidden units per CTA (NH2 / CLS)
#define ROWS 128     // gate rows per CTA (4 * UPC)

#define HPITCH 264                    // padded h row (per lane)
#define HBUF (LANES * HPITCH)         // 2112 floats per buffer
#define REDP 9                        // padded red lane dim
#define REDK (ROWS * REDP)            // 1152 floats per k-slice

// dynamic smem layout (floats)
#define SW_OFF 0                          // 32768 floats: W_s[ks][j][kq][rg][4]
#define HB_OFF 32768                      // 2 * 2112
#define RED_OFF (HB_OFF + 2 * HBUF)       // 36992, 8 * 1152
#define DSM_FLOATS (RED_OFF + 8 * REDK)   // 46208 floats = 184832 B

// ------------------- scratch (static device allocations) -------------------
__device__ float g_G[2][NM][NG];       // precomputed x@wih^T + bih + bhh  (134 MB)
__device__ float g_lstm[NM][2 * NH2];  // concat hidden states            (33.5 MB)
__device__ float g_feats[NM][NT];      // emission scores                 (0.66 MB)

__device__ __forceinline__ float sigf(float x) { return 1.0f / (1.0f + expf(-x)); }

__device__ __forceinline__ unsigned smem_u32(const void* p) {
    unsigned a;
    asm("{ .reg .u64 t; cvta.to.shared.u64 t, %1; cvt.u32.u64 %0, t; }" : "=r"(a) : "l"(p));
    return a;
}
__device__ __forceinline__ unsigned ctarank() {
    unsigned r; asm("mov.u32 %0, %%cluster_ctarank;" : "=r"(r)); return r;
}
// packed f32x2 fma: d = a*b + d (elementwise on 2 packed fp32)
__device__ __forceinline__ void ffma2(unsigned long long& d,
                                      unsigned long long a, unsigned long long b) {
    asm("fma.rn.f32x2 %0, %1, %2, %0;" : "+l"(d) : "l"(a), "l"(b));
}
__device__ __forceinline__ float hadd2(unsigned long long v) {
    float lo, hi;
    asm("mov.b64 {%0, %1}, %2;" : "=f"(lo), "=f"(hi) : "l"(v));
    return lo + hi;
}

// ------------------- input projection GEMM --------------------------------
__global__ __launch_bounds__(256) void k_input_gemm(
    const int* __restrict__ tok, const float* __restrict__ emb,
    const float* __restrict__ wih, const float* __restrict__ bih,
    const float* __restrict__ bhh, int dir) {
    __shared__ float As[8][128];
    __shared__ float Bs[8][128];
    __shared__ int stok[128];

    const int t0 = blockIdx.x * 128;
    const int j0 = blockIdx.y * 128;
    const int tid = threadIdx.x;
    if (tid < 128) stok[tid] = tok[t0 + tid];
    __syncthreads();

    const int tx = tid & 15;
    const int ty = tid >> 4;
    const int r = tid >> 1;
    const int q = tid & 1;

    float acc[8][8];
    #pragma unroll
    for (int i = 0; i < 8; ++i)
        #pragma unroll
        for (int j = 0; j < 8; ++j) acc[i][j] = 0.0f;

    for (int k0 = 0; k0 < NE; k0 += 8) {
        const int kc = k0 + q * 4;
        float4 av = make_float4(0.f, 0.f, 0.f, 0.f);
        float4 bv = make_float4(0.f, 0.f, 0.f, 0.f);
        if (kc < NE) {
            av = *(const float4*)(emb + (size_t)stok[r] * NE + kc);
            bv = *(const float4*)(wih + (size_t)(j0 + r) * NE + kc);
        }
        __syncthreads();
        As[q * 4 + 0][r] = av.x; As[q * 4 + 1][r] = av.y;
        As[q * 4 + 2][r] = av.z; As[q * 4 + 3][r] = av.w;
        Bs[q * 4 + 0][r] = bv.x; Bs[q * 4 + 1][r] = bv.y;
        Bs[q * 4 + 2][r] = bv.z; Bs[q * 4 + 3][r] = bv.w;
        __syncthreads();
        #pragma unroll
        for (int kk = 0; kk < 8; ++kk) {
            float a[8], b[8];
            *(float4*)&a[0] = *(const float4*)&As[kk][ty * 8];
            *(float4*)&a[4] = *(const float4*)&As[kk][ty * 8 + 4];
            *(float4*)&b[0] = *(const float4*)&Bs[kk][tx * 8];
            *(float4*)&b[4] = *(const float4*)&Bs[kk][tx * 8 + 4];
            #pragma unroll
            for (int i = 0; i < 8; ++i)
                #pragma unroll
                for (int j = 0; j < 8; ++j)
                    acc[i][j] = fmaf(a[i], b[j], acc[i][j]);
        }
    }

    const int jj = j0 + tx * 8;
    float bsum[8];
    #pragma unroll
    for (int j = 0; j < 8; ++j) bsum[j] = bih[jj + j] + bhh[jj + j];
    #pragma unroll
    for (int i = 0; i < 8; ++i) {
        float* dst = &g_G[dir][t0 + ty * 8 + i][jj];
        #pragma unroll
        for (int j = 0; j < 8; ++j) dst[j] = acc[i][j] + bsum[j];
    }
}

// ------------------- clustered recurrent LSTM ------------------------------
// 128 CTAs = 16 clusters of 8. CTA rank owns 32 hidden units (128 gate rows);
// weight slice SMEM-resident in warp-tiled layout. Per step:
//   matvec: warp = k-slice (32 k), thread = 8 rows x 4 lanes, f32x2 packed FMA
//   reduce: partials staged to smem, phase-2 thread = (unit, lane) sums 8 slices
//   cell + DSMEM h-broadcast to 8 CTAs + cluster barrier.
__global__ __launch_bounds__(256, 1) __cluster_dims__(CLS, 1, 1)
void k_lstm(const float* __restrict__ whh_f, const float* __restrict__ whh_b,
            const float* __restrict__ h0, const float* __restrict__ c0) {
    extern __shared__ float dsm[];
    const int tid = threadIdx.x;
    const unsigned rank = ctarank();
    const int cid = blockIdx.x >> 3;
    const int dir = cid >> 3;
    const int bg0 = (cid & 7) * LANES;
    const int u0 = rank * UPC;

    const float* __restrict__ whh = dir ? whh_b : whh_f;

    // ---- stage weight slice into warp-tiled layout:
    // W_s float-index = (ks*64 + j*8 + kq)*64 + rg*4 + c
    //   encodes W[row=rg*8+j][k=ks*32+kq*4+c], row->gate grow below
    for (int idx = tid; idx < ROWS * NH2; idx += 256) {
        const int c = idx & 3;
        const int rg = (idx >> 2) & 15;
        const int kq = (idx >> 6) & 7;
        const int j = (idx >> 9) & 7;
        const int ks = idx >> 12;
        const int row = rg * 8 + j;
        const int grow = ((row >> 5) << 8) + u0 + (row & 31);
        const int k = ks * 32 + kq * 4 + c;
        dsm[SW_OFF + idx] = whh[(size_t)grow * NH2 + k];
    }
    // ---- init h buffer 0: hT[lane][k]
    for (int jdx = tid; jdx < LANES * NH2; jdx += 256) {
        const int l = jdx >> 8, k = jdx & 255;
        dsm[HB_OFF + l * HPITCH + k] = h0[(size_t)(dir * NB + bg0 + l) * NH2 + k];
    }
    // ---- phase-2 role + cell state
    const int eu = tid >> 3, el = tid & 7;
    float c = c0[(size_t)(dir * NB + bg0 + el) * NH2 + u0 + eu];

    // ---- peer hbuf base addresses
    const unsigned hb_local = smem_u32(&dsm[HB_OFF]);
    unsigned hb_peer[CLS];
    #pragma unroll
    for (int j = 0; j < CLS; ++j)
        asm("mapa.shared::cluster.u32 %0, %1, %2;"
            : "=r"(hb_peer[j]) : "r"(hb_local), "r"(j));

    // ---- matvec role
    const int ks = tid >> 5;
    const int lane = tid & 31;
    const int lg = lane >> 4;       // 0..1 (4-lane group)
    const int rg = lane & 15;       // 0..15 (8-row group)
    const float* __restrict__ Gd = &g_G[dir][0][0];
    const int wbase = SW_OFF + ks * 4096 + rg * 4;
    const int hbase = HB_OFF + lg * 4 * HPITCH + ks * 32;

    __syncthreads();
    asm volatile("barrier.cluster.arrive.aligned;" ::: "memory");
    asm volatile("barrier.cluster.wait.aligned;" ::: "memory");

    int p = 0;
    for (int si = 0; si < NS; ++si) {
        const int s = dir ? (NS - 1 - si) : si;

        // prefetch input-gate contributions for phase-2 (hidden by matvec)
        const float* Gp = Gd + (size_t)(s * NB + bg0 + el) * NG + u0 + eu;
        const float gin0 = Gp[0];
        const float gin1 = Gp[256];
        const float gin2 = Gp[512];
        const float gin3 = Gp[768];

        // ---- matvec: accp[j][li] over 32 k, packed f32x2 pairs
        unsigned long long accp[32];
        #pragma unroll
        for (int i = 0; i < 32; ++i) accp[i] = 0ull;

        const float* Hb = &dsm[hbase + p * HBUF];
        #pragma unroll
        for (int kq = 0; kq < 8; ++kq) {
            ulonglong2 hq[4];
            #pragma unroll
            for (int li = 0; li < 4; ++li)
                hq[li] = *(const ulonglong2*)(Hb + li * HPITCH + kq * 4);
            #pragma unroll
            for (int j = 0; j < 8; ++j) {
                const ulonglong2 wv =
                    *(const ulonglong2*)&dsm[wbase + (j * 8 + kq) * 64];
                #pragma unroll
                for (int li = 0; li < 4; ++li) {
                    ffma2(accp[j * 4 + li], wv.x, hq[li].x);
                    ffma2(accp[j * 4 + li], wv.y, hq[li].y);
                }
            }
        }

        // ---- stage partials: red[ks][row][lane] (pitch REDP)
        #pragma unroll
        for (int j = 0; j < 8; ++j) {
            const int r = rg * 8 + j;
            float* rp = &dsm[RED_OFF + ks * REDK + r * REDP + lg * 4];
            #pragma unroll
            for (int li = 0; li < 4; ++li) rp[li] = hadd2(accp[j * 4 + li]);
        }
        __syncthreads();

        // ---- phase 2: reduce 8 k-slices, LSTM cell for (unit eu, lane el)
        {
            float g0 = gin0, g1 = gin1, g2 = gin2, g3 = gin3;
            const float* rb = &dsm[RED_OFF + el];
            #pragma unroll
            for (int kk = 0; kk < 8; ++kk) {
                const float* rk = rb + kk * REDK;
                g0 += rk[(eu) * REDP];
                g1 += rk[(32 + eu) * REDP];
                g2 += rk[(64 + eu) * REDP];
                g3 += rk[(96 + eu) * REDP];
            }
            const float iv = sigf(g0), fv = sigf(g1);
            const float gv = tanhf(g2), ov = sigf(g3);
            c = fv * c + iv * gv;
            const float h = ov * tanhf(c);

            // broadcast new h to all 8 CTAs (buffer p^1), hT[el][u0+eu]
            const unsigned off = (((p ^ 1) * HBUF) + el * HPITCH + u0 + eu) * 4u;
            #pragma unroll
            for (int j = 0; j < CLS; ++j)
                asm volatile("st.shared::cluster.f32 [%0], %1;"
                             :: "r"(hb_peer[j] + off), "f"(h) : "memory");

            g_lstm[s * NB + bg0 + el][dir * NH2 + u0 + eu] = h;
        }

        // ---- cluster barrier (release peer stores / acquire for next read)
        asm volatile("barrier.cluster.arrive.aligned;" ::: "memory");
        asm volatile("barrier.cluster.wait.aligned;" ::: "memory");
        p ^= 1;
    }
}

// ------------------- emission features: lstm_out @ W_out^T + b_out ---------
__global__ __launch_bounds__(256) void k_feats(const float* __restrict__ Wout,
                                               const float* __restrict__ bout) {
    __shared__ float sW[NT][2 * NH2];
    const int tid = threadIdx.x;
    for (int i = tid; i < NT * 2 * NH2; i += 256) sW[i / (2 * NH2)][i % (2 * NH2)] = Wout[i];
    __syncthreads();

    const int warp = tid >> 5, lane = tid & 31;
    const int n = blockIdx.x * 8 + warp;
    const float4* row = (const float4*)&g_lstm[n][0];

    float pAcc[NT];
    #pragma unroll
    for (int t = 0; t < NT; ++t) pAcc[t] = 0.0f;
    for (int q = lane; q < 128; q += 32) {
        const float4 v = row[q];
        #pragma unroll
        for (int t = 0; t < NT; ++t) {
            const float4 w = ((const float4*)&sW[t][0])[q];
            pAcc[t] += v.x * w.x + v.y * w.y + v.z * w.z + v.w * w.w;
        }
    }
    #pragma unroll
    for (int off = 16; off; off >>= 1)
        #pragma unroll
        for (int t = 0; t < NT; ++t)
            pAcc[t] += __shfl_down_sync(0xffffffffu, pAcc[t], off);
    if (lane == 0) {
        #pragma unroll
        for (int t = 0; t < NT; ++t) g_feats[n][t] = pAcc[t] + bout[t];
    }
}

// ------------------- Viterbi decode (1 warp per batch element) -------------
__global__ void k_viterbi(const float* __restrict__ trans, float* __restrict__ out) {
    const int b = blockIdx.x;
    const int lane = threadIdx.x;
    __shared__ float st[NT * NT];
    __shared__ unsigned char bp[NS][NT];
    for (int i = lane; i < NT * NT; i += 32) st[i] = trans[i];
    __syncwarp();

    float fv = (lane == IDX_START) ? 0.0f : -10000.0f;
    for (int s = 0; s < NS; ++s) {
        float best = -3.4e38f;
        int barg = 0;
        const float cur = fv;
        #pragma unroll
        for (int p = 0; p < NT; ++p) {
            const float fp = __shfl_sync(0xffffffffu, cur, p);
            if (lane < NT) {
                const float v = fp + st[lane * NT + p];
                if (v > best) { best = v; barg = p; }
            }
        }
        float feat = 0.0f;
        if (lane < NT) feat = g_feats[b * NS + s][lane];
        fv = best + feat;
        if (lane < NT) bp[s][lane] = (unsigned char)barg;
        __syncwarp();
    }
    float m = (lane < NT) ? (fv + st[IDX_STOP * NT + lane]) : -3.4e38f;
    int mi = lane;
    #pragma unroll
    for (int off = 16; off; off >>= 1) {
        const float om = __shfl_down_sync(0xffffffffu, m, off);
        const int oi = __shfl_down_sync(0xffffffffu, mi, off);
        if (om > m || (om == m && oi < mi)) { m = om; mi = oi; }
    }
    if (lane == 0) {
        out[b] = m;
        int best = mi;
        for (int s = NS - 1; s >= 0; --s) {
            out[NB + b * NS + s] = (float)best;
            best = bp[s][best];
        }
    }
}

// ------------------- launcher ----------------------------------------------
extern "C" void kernel_launch(void* const* d_in, const int* in_sizes, int n_in,
                              void* d_out, int out_size) {
    const int*   sent  = (const int*)d_in[0];
    const float* emb   = (const float*)d_in[1];
    const float* wih_f = (const float*)d_in[2];
    const float* whh_f = (const float*)d_in[3];
    const float* bih_f = (const float*)d_in[4];
    const float* bhh_f = (const float*)d_in[5];
    const float* wih_b = (const float*)d_in[6];
    const float* whh_b = (const float*)d_in[7];
    const float* bih_b = (const float*)d_in[8];
    const float* bhh_b = (const float*)d_in[9];
    const float* Wout  = (const float*)d_in[10];
    const float* bout  = (const float*)d_in[11];

    const float *trans, *h0, *c0;
    if (n_in > 12 && in_sizes[12] == NT * NT) {
        trans = (const float*)d_in[12];
        h0    = (const float*)d_in[13];
        c0    = (const float*)d_in[14];
    } else {
        h0    = (const float*)d_in[12];
        c0    = (const float*)d_in[13];
        trans = (const float*)d_in[14];
    }

    static int smem_set = 0;
    const int lstm_smem = DSM_FLOATS * (int)sizeof(float);  // ~180.5 KB
    if (!smem_set) {
        cudaFuncSetAttribute(k_lstm, cudaFuncAttributeMaxDynamicSharedMemorySize,
                             lstm_smem);
        smem_set = 1;
    }

    {
        dim3 gg(NM / 128, NG / 128);
        k_input_gemm<<<gg, 256>>>(sent, emb, wih_f, bih_f, bhh_f, 0);
        k_input_gemm<<<gg, 256>>>(sent, emb, wih_b, bih_b, bhh_b, 1);
    }
    k_lstm<<<128, 256, lstm_smem>>>(whh_f, whh_b, h0, c0);
    k_feats<<<NM / 8, 256>>>(Wout, bout);
    k_viterbi<<<NB, 32>>>(trans, (float*)d_out);
}

// round 10
// speedup vs baseline: 3.9001x; 1.1453x over previous
#include <cuda_runtime.h>
#include <math.h>

#define NS 256       // sequence length S
#define NB 64        // batch B
#define NE 300       // embedding dim E
#define NH2 256      // hidden per direction
#define NG 1024      // 4*NH2 gates
#define NM 16384     // S*B flattened rows
#define NT 10        // tags
#define IDX_START 8
#define IDX_STOP 9

// LSTM cluster geometry
#define CLS 8        // CTAs per cluster
#define LANES 8      // batch lanes per cluster
#define UPC 32       // hidden units per CTA (NH2 / CLS)
#define ROWS 128     // gate rows per CTA (4 * UPC)

#define HPITCH 264                    // padded h row (per lane)
#define HBUF (LANES * HPITCH)         // 2112 floats per buffer
#define ELP 132                       // red: el pitch (132 fl = 528 B, 16B-mult)
#define REDK (LANES * ELP)            // 1056 floats per k-slice
#define WBLK 576                      // 16 rg * 36 (padded k pitch)

// dynamic smem layout (floats)
#define SW_OFF 0                          // 16*4*576 = 36864 floats
#define HB_OFF 36864                      // 2 * 2112
#define RED_OFF (HB_OFF + 2 * HBUF)       // 41088, 8 * 1056
#define DSM_FLOATS (RED_OFF + 8 * REDK)   // 49536 floats = 198144 B

// ------------------- scratch (static device allocations) -------------------
// G2 layout: [dir][s][cb][rank][gate*32+eu][el]  (contiguous 4KB per CTA-step)
__device__ __align__(256) float g_G2[2][NS][8][8][4 * UPC * LANES];  // 134 MB
__device__ __align__(256) float g_lstm[NM][2 * NH2];                 // 33.5 MB
__device__ __align__(256) float g_feats[NM][NT];                     // 0.66 MB

__device__ __forceinline__ float sigf(float x) { return 1.0f / (1.0f + expf(-x)); }

__device__ __forceinline__ unsigned smem_u32(const void* p) {
    unsigned a;
    asm("{ .reg .u64 t; cvta.to.shared.u64 t, %1; cvt.u32.u64 %0, t; }" : "=r"(a) : "l"(p));
    return a;
}
__device__ __forceinline__ unsigned ctarank() {
    unsigned r; asm("mov.u32 %0, %%cluster_ctarank;" : "=r"(r)); return r;
}
__device__ __forceinline__ void ffma2(unsigned long long& d,
                                      unsigned long long a, unsigned long long b) {
    asm("fma.rn.f32x2 %0, %1, %2, %0;" : "+l"(d) : "l"(a), "l"(b));
}
__device__ __forceinline__ float hadd2(unsigned long long v) {
    float lo, hi;
    asm("mov.b64 {%0, %1}, %2;" : "=f"(lo), "=f"(hi) : "l"(v));
    return lo + hi;
}

// ------------------- input projection GEMM --------------------------------
// C[t][col] = sum_e emb[tok[t]][e] * wih[col][e] + (bih+bhh)[col]
// Writes directly into the lstm-friendly g_G2 layout.
__global__ __launch_bounds__(256) void k_input_gemm(
    const int* __restrict__ tok, const float* __restrict__ emb,
    const float* __restrict__ wih, const float* __restrict__ bih,
    const float* __restrict__ bhh, int dir) {
    __shared__ float As[8][128];
    __shared__ float Bs[8][128];
    __shared__ int stok[128];

    const int t0 = blockIdx.x * 128;
    const int j0 = blockIdx.y * 128;
    const int tid = threadIdx.x;
    if (tid < 128) stok[tid] = tok[t0 + tid];
    __syncthreads();

    const int tx = tid & 15;
    const int ty = tid >> 4;
    const int r = tid >> 1;
    const int q = tid & 1;

    float acc[8][8];
    #pragma unroll
    for (int i = 0; i < 8; ++i)
        #pragma unroll
        for (int j = 0; j < 8; ++j) acc[i][j] = 0.0f;

    for (int k0 = 0; k0 < NE; k0 += 8) {
        const int kc = k0 + q * 4;
        float4 av = make_float4(0.f, 0.f, 0.f, 0.f);
        float4 bv = make_float4(0.f, 0.f, 0.f, 0.f);
        if (kc < NE) {
            av = *(const float4*)(emb + (size_t)stok[r] * NE + kc);
            bv = *(const float4*)(wih + (size_t)(j0 + r) * NE + kc);
        }
        __syncthreads();
        As[q * 4 + 0][r] = av.x; As[q * 4 + 1][r] = av.y;
        As[q * 4 + 2][r] = av.z; As[q * 4 + 3][r] = av.w;
        Bs[q * 4 + 0][r] = bv.x; Bs[q * 4 + 1][r] = bv.y;
        Bs[q * 4 + 2][r] = bv.z; Bs[q * 4 + 3][r] = bv.w;
        __syncthreads();
        #pragma unroll
        for (int kk = 0; kk < 8; ++kk) {
            float a[8], b[8];
            *(float4*)&a[0] = *(const float4*)&As[kk][ty * 8];
            *(float4*)&a[4] = *(const float4*)&As[kk][ty * 8 + 4];
            *(float4*)&b[0] = *(const float4*)&Bs[kk][tx * 8];
            *(float4*)&b[4] = *(const float4*)&Bs[kk][tx * 8 + 4];
            #pragma unroll
            for (int i = 0; i < 8; ++i)
                #pragma unroll
                for (int j = 0; j < 8; ++j)
                    acc[i][j] = fmaf(a[i], b[j], acc[i][j]);
        }
    }

    // epilogue: thread covers t = t0+ty*8+i (i=0..7 -> el), col = j0+tx*8+j (-> eu)
    const int jj = j0 + tx * 8;
    float bsum[8];
    #pragma unroll
    for (int j = 0; j < 8; ++j) bsum[j] = bih[jj + j] + bhh[jj + j];

    const int tb = t0 + ty * 8;          // aligned to 8 -> el = i
    const int s = tb >> 6;
    const int cb = (tb >> 3) & 7;
    const int gate = jj >> 8;
    const int rank = (jj >> 5) & 7;
    const int eu0 = jj & 31;             // in {0,8,16,24}; j<8 stays in-range
    float* base2 = &g_G2[dir][s][cb][rank][0] + gate * 256 + eu0 * 8;

    #pragma unroll
    for (int j = 0; j < 8; ++j) {
        float4 lo = make_float4(acc[0][j] + bsum[j], acc[1][j] + bsum[j],
                                acc[2][j] + bsum[j], acc[3][j] + bsum[j]);
        float4 hi = make_float4(acc[4][j] + bsum[j], acc[5][j] + bsum[j],
                                acc[6][j] + bsum[j], acc[7][j] + bsum[j]);
        *(float4*)(base2 + j * 8) = lo;
        *(float4*)(base2 + j * 8 + 4) = hi;
    }
}

// ------------------- clustered recurrent LSTM ------------------------------
// 128 CTAs = 16 clusters of 8, 512 threads (16 warps, 4/SMSP).
// Matvec: warp=(ks,half), thread=(lg,rg) -> 4 rows x 4 lanes x 32 k, f32x2 FMA.
// Partials staged red[ks][el(pitch 132)][row] -- 16B-aligned rows, conflict-free
// STS.128 (phase C) and conflict-free scalar LDS (phase D).
__global__ __launch_bounds__(512, 1) __cluster_dims__(CLS, 1, 1)
void k_lstm(const float* __restrict__ whh_f, const float* __restrict__ whh_b,
            const float* __restrict__ h0, const float* __restrict__ c0) {
    extern __shared__ float dsm[];
    const int tid = threadIdx.x;
    const unsigned rank = ctarank();
    const int cid = blockIdx.x >> 3;
    const int dir = cid >> 3;
    const int cb = cid & 7;
    const int bg0 = cb * LANES;
    const int u0 = rank * UPC;

    const float* __restrict__ whh = dir ? whh_b : whh_f;

    // ---- stage weight slice: W2[(ks*2+half)*4 + j][rg][kk(pad 36)]
    for (int idx = tid; idx < ROWS * NH2; idx += 512) {
        const int row = idx >> 8;          // local gate row 0..127
        const int k = idx & 255;
        const int half = row >> 6, rp = row & 63;
        const int rg = rp >> 2, j = rp & 3;
        const int ks = k >> 5, kk = k & 31;
        const int grow = ((row >> 5) << 8) + u0 + (row & 31);
        dsm[SW_OFF + ((ks * 2 + half) * 4 + j) * WBLK + rg * 36 + kk] =
            whh[(size_t)grow * NH2 + k];
    }
    // ---- init h buffer 0: hT[el][k]
    for (int jdx = tid; jdx < LANES * NH2; jdx += 512) {
        const int l = jdx >> 8, k = jdx & 255;
        dsm[HB_OFF + l * HPITCH + k] = h0[(size_t)(dir * NB + bg0 + l) * NH2 + k];
    }
    // ---- phase-2 role (tid<256): (unit eu, lane el)
    const int eu = tid >> 3, el = tid & 7;
    float c = 0.0f;
    if (tid < 256)
        c = c0[(size_t)(dir * NB + bg0 + el) * NH2 + u0 + eu];

    // ---- peer hbuf base addresses
    const unsigned hb_local = smem_u32(&dsm[HB_OFF]);
    unsigned hb_peer[CLS];
    #pragma unroll
    for (int j = 0; j < CLS; ++j)
        asm("mapa.shared::cluster.u32 %0, %1, %2;"
            : "=r"(hb_peer[j]) : "r"(hb_local), "r"(j));

    // ---- matvec role
    const int w = tid >> 5;
    const int ks = w >> 1;
    const int half = w & 1;
    const int lane = tid & 31;
    const int lg = lane >> 4;       // 0..1 (4-lane group)
    const int rg = lane & 15;       // 0..15 (4-row group)
    const int wb0 = SW_OFF + (ks * 2 + half) * 4 * WBLK + rg * 36;
    const int hbase = HB_OFF + lg * 4 * HPITCH + ks * 32;
    // phase-C store base: red[ks][el = lg*4 + li][row = half*64 + rg*4 .. +3]
    const int cbase = RED_OFF + ks * REDK + lg * 4 * ELP + half * 64 + rg * 4;

    // CTA-step base into g_G2
    const float* __restrict__ G2 = &g_G2[dir][0][cb][rank][0];

    __syncthreads();
    asm volatile("barrier.cluster.arrive.aligned;" ::: "memory");
    asm volatile("barrier.cluster.wait.aligned;" ::: "memory");

    int p = 0;
    for (int si = 0; si < NS; ++si) {
        const int s = dir ? (NS - 1 - si) : si;

        // phase A (tid<256): coalesced input-gate loads
        float gin0 = 0.f, gin1 = 0.f, gin2 = 0.f, gin3 = 0.f;
        if (tid < 256) {
            const float* Gp = G2 + (size_t)s * (8 * 8 * 1024) + tid;
            gin0 = Gp[0];
            gin1 = Gp[256];
            gin2 = Gp[512];
            gin3 = Gp[768];
        }

        // phase B: matvec, 4 rows (j) x 4 lanes (li) x 32 k
        unsigned long long accp[16];
        #pragma unroll
        for (int i = 0; i < 16; ++i) accp[i] = 0ull;

        const float* Hb = &dsm[hbase + p * HBUF];
        #pragma unroll
        for (int kq = 0; kq < 8; ++kq) {
            ulonglong2 hq[4];
            #pragma unroll
            for (int li = 0; li < 4; ++li)
                hq[li] = *(const ulonglong2*)(Hb + li * HPITCH + kq * 4);
            #pragma unroll
            for (int j = 0; j < 4; ++j) {
                const ulonglong2 wv =
                    *(const ulonglong2*)&dsm[wb0 + j * WBLK + kq * 4];
                #pragma unroll
                for (int li = 0; li < 4; ++li) {
                    ffma2(accp[j * 4 + li], wv.x, hq[li].x);
                    ffma2(accp[j * 4 + li], wv.y, hq[li].y);
                }
            }
        }

        // phase C: stage partials  red[ks][el][row], one float4 (4 rows) per el
        #pragma unroll
        for (int li = 0; li < 4; ++li) {
            float4 v = make_float4(hadd2(accp[0 * 4 + li]), hadd2(accp[1 * 4 + li]),
                                   hadd2(accp[2 * 4 + li]), hadd2(accp[3 * 4 + li]));
            *(float4*)&dsm[cbase + li * ELP] = v;  // 16B-aligned (ELP=132)
        }
        __syncthreads();

        // phase D (tid<256): reduce 8 k-slices + LSTM cell + h broadcast
        if (tid < 256) {
            float g0 = gin0, g1 = gin1, g2 = gin2, g3 = gin3;
            const float* rb = &dsm[RED_OFF + el * ELP];
            #pragma unroll
            for (int kk = 0; kk < 8; ++kk) {
                const float* rk = rb + kk * REDK;
                g0 += rk[eu];
                g1 += rk[32 + eu];
                g2 += rk[64 + eu];
                g3 += rk[96 + eu];
            }
            const float iv = sigf(g0), fv = sigf(g1);
            const float gv = tanhf(g2), ov = sigf(g3);
            c = fv * c + iv * gv;
            const float h = ov * tanhf(c);

            const unsigned off = (((p ^ 1) * HBUF) + el * HPITCH + u0 + eu) * 4u;
            #pragma unroll
            for (int j = 0; j < CLS; ++j)
                asm volatile("st.shared::cluster.f32 [%0], %1;"
                             :: "r"(hb_peer[j] + off), "f"(h) : "memory");
        }
        __syncthreads();   // own h-stores visible locally for phase E

        // phase E (tid<256): coalesced g_lstm writeback from local buffer p^1
        if (tid < 256) {
            const int el2 = tid >> 5, ul = tid & 31;
            const float hv = dsm[HB_OFF + (p ^ 1) * HBUF + el2 * HPITCH + u0 + ul];
            g_lstm[s * NB + bg0 + el2][dir * NH2 + u0 + ul] = hv;
        }

        // phase F: cluster barrier (release peer stores / acquire for next read)
        asm volatile("barrier.cluster.arrive.aligned;" ::: "memory");
        asm volatile("barrier.cluster.wait.aligned;" ::: "memory");
        p ^= 1;
    }
}

// ------------------- emission features: lstm_out @ W_out^T + b_out ---------
__global__ __launch_bounds__(256) void k_feats(const float* __restrict__ Wout,
                                               const float* __restrict__ bout) {
    __shared__ float sW[NT][2 * NH2];
    const int tid = threadIdx.x;
    for (int i = tid; i < NT * 2 * NH2; i += 256) sW[i / (2 * NH2)][i % (2 * NH2)] = Wout[i];
    __syncthreads();

    const int warp = tid >> 5, lane = tid & 31;
    const int n = blockIdx.x * 8 + warp;
    const float4* row = (const float4*)&g_lstm[n][0];

    float pAcc[NT];
    #pragma unroll
    for (int t = 0; t < NT; ++t) pAcc[t] = 0.0f;
    for (int q = lane; q < 128; q += 32) {
        const float4 v = row[q];
        #pragma unroll
        for (int t = 0; t < NT; ++t) {
            const float4 wv = ((const float4*)&sW[t][0])[q];
            pAcc[t] += v.x * wv.x + v.y * wv.y + v.z * wv.z + v.w * wv.w;
        }
    }
    #pragma unroll
    for (int off = 16; off; off >>= 1)
        #pragma unroll
        for (int t = 0; t < NT; ++t)
            pAcc[t] += __shfl_down_sync(0xffffffffu, pAcc[t], off);
    if (lane == 0) {
        #pragma unroll
        for (int t = 0; t < NT; ++t) g_feats[n][t] = pAcc[t] + bout[t];
    }
}

// ------------------- Viterbi decode (1 warp per batch element) -------------
__global__ void k_viterbi(const float* __restrict__ trans, float* __restrict__ out) {
    const int b = blockIdx.x;
    const int lane = threadIdx.x;
    __shared__ float st[NT * NT];
    __shared__ unsigned char bp[NS][NT];
    for (int i = lane; i < NT * NT; i += 32) st[i] = trans[i];
    __syncwarp();

    float fv = (lane == IDX_START) ? 0.0f : -10000.0f;
    for (int s = 0; s < NS; ++s) {
        float best = -3.4e38f;
        int barg = 0;
        const float cur = fv;
        #pragma unroll
        for (int p = 0; p < NT; ++p) {
            const float fp = __shfl_sync(0xffffffffu, cur, p);
            if (lane < NT) {
                const float v = fp + st[lane * NT + p];
                if (v > best) { best = v; barg = p; }
            }
        }
        float feat = 0.0f;
        if (lane < NT) feat = g_feats[b * NS + s][lane];
        fv = best + feat;
        if (lane < NT) bp[s][lane] = (unsigned char)barg;
        __syncwarp();
    }
    float m = (lane < NT) ? (fv + st[IDX_STOP * NT + lane]) : -3.4e38f;
    int mi = lane;
    #pragma unroll
    for (int off = 16; off; off >>= 1) {
        const float om = __shfl_down_sync(0xffffffffu, m, off);
        const int oi = __shfl_down_sync(0xffffffffu, mi, off);
        if (om > m || (om == m && oi < mi)) { m = om; mi = oi; }
    }
    if (lane == 0) {
        out[b] = m;
        int best = mi;
        for (int s = NS - 1; s >= 0; --s) {
            out[NB + b * NS + s] = (float)best;
            best = bp[s][best];
        }
    }
}

// ------------------- launcher ----------------------------------------------
extern "C" void kernel_launch(void* const* d_in, const int* in_sizes, int n_in,
                              void* d_out, int out_size) {
    const int*   sent  = (const int*)d_in[0];
    const float* emb   = (const float*)d_in[1];
    const float* wih_f = (const float*)d_in[2];
    const float* whh_f = (const float*)d_in[3];
    const float* bih_f = (const float*)d_in[4];
    const float* bhh_f = (const float*)d_in[5];
    const float* wih_b = (const float*)d_in[6];
    const float* whh_b = (const float*)d_in[7];
    const float* bih_b = (const float*)d_in[8];
    const float* bhh_b = (const float*)d_in[9];
    const float* Wout  = (const float*)d_in[10];
    const float* bout  = (const float*)d_in[11];

    const float *trans, *h0, *c0;
    if (n_in > 12 && in_sizes[12] == NT * NT) {
        trans = (const float*)d_in[12];
        h0    = (const float*)d_in[13];
        c0    = (const float*)d_in[14];
    } else {
        h0    = (const float*)d_in[12];
        c0    = (const float*)d_in[13];
        trans = (const float*)d_in[14];
    }

    static int smem_set = 0;
    const int lstm_smem = DSM_FLOATS * (int)sizeof(float);  // ~193.5 KB
    if (!smem_set) {
        cudaFuncSetAttribute(k_lstm, cudaFuncAttributeMaxDynamicSharedMemorySize,
                             lstm_smem);
        smem_set = 1;
    }

    {
        dim3 gg(NM / 128, NG / 128);
        k_input_gemm<<<gg, 256>>>(sent, emb, wih_f, bih_f, bhh_f, 0);
        k_input_gemm<<<gg, 256>>>(sent, emb, wih_b, bih_b, bhh_b, 1);
    }
    k_lstm<<<128, 512, lstm_smem>>>(whh_f, whh_b, h0, c0);
    k_feats<<<NM / 8, 256>>>(Wout, bout);
    k_viterbi<<<NB, 32>>>(trans, (float*)d_out);
}

// round 11
// speedup vs baseline: 4.0921x; 1.0492x over previous
#include <cuda_runtime.h>
#include <math.h>

#define NS 256       // sequence length S
#define NB 64        // batch B
#define NE 300       // embedding dim E
#define NH2 256      // hidden per direction
#define NG 1024      // 4*NH2 gates
#define NM 16384     // S*B flattened rows
#define NT 10        // tags
#define IDX_START 8
#define IDX_STOP 9

// LSTM cluster geometry
#define CLS 8        // CTAs per cluster
#define LANES 8      // batch lanes per cluster
#define UPC 32       // hidden units per CTA (NH2 / CLS)
#define ROWS 128     // gate rows per CTA (4 * UPC)

#define HPITCH 264                    // padded h row (per lane)
#define HBUF (LANES * HPITCH)         // 2112 floats per buffer
#define ELP 132                       // red: el pitch (132 fl = 528 B, 16B-mult)
#define REDK (LANES * ELP)            // 1056 floats per k-slice
#define WPITCH 34                     // padded k pitch (8B-aligned, bank rg*2)
#define WBLK (16 * WPITCH)            // 544 floats per (ks,half,j) block

// dynamic smem layout (floats)
#define SW_OFF 0                          // 64 * 544 = 34816 floats
#define HB_OFF 34816                      // 2 * 2112
#define RED_OFF (HB_OFF + 2 * HBUF)       // 39040, 8 * 1056
#define DSM_FLOATS (RED_OFF + 8 * REDK)   // 47488 floats = 189952 B

// ------------------- scratch (static device allocations) -------------------
// G2 layout: [dir][s][cb][rank][gate*32+eu][el]  (contiguous 4KB per CTA-step)
__device__ __align__(256) float g_G2[2][NS][8][8][4 * UPC * LANES];  // 134 MB
__device__ __align__(256) float g_lstm[NM][2 * NH2];                 // 33.5 MB
__device__ __align__(256) float g_feats[NM][NT];                     // 0.66 MB

__device__ __forceinline__ float sigf(float x) { return 1.0f / (1.0f + expf(-x)); }

__device__ __forceinline__ unsigned smem_u32(const void* p) {
    unsigned a;
    asm("{ .reg .u64 t; cvta.to.shared.u64 t, %1; cvt.u32.u64 %0, t; }" : "=r"(a) : "l"(p));
    return a;
}
__device__ __forceinline__ unsigned ctarank() {
    unsigned r; asm("mov.u32 %0, %%cluster_ctarank;" : "=r"(r)); return r;
}
__device__ __forceinline__ void ffma2(unsigned long long& d,
                                      unsigned long long a, unsigned long long b) {
    asm("fma.rn.f32x2 %0, %1, %2, %0;" : "+l"(d) : "l"(a), "l"(b));
}
__device__ __forceinline__ float hadd2(unsigned long long v) {
    float lo, hi;
    asm("mov.b64 {%0, %1}, %2;" : "=f"(lo), "=f"(hi) : "l"(v));
    return lo + hi;
}
__device__ __forceinline__ unsigned long long pk2(float x) {
    unsigned long long d;
    asm("mov.b64 %0, {%1, %1};" : "=l"(d) : "f"(x));
    return d;
}
__device__ __forceinline__ void upk2(unsigned long long v, float& lo, float& hi) {
    asm("mov.b64 {%0, %1}, %2;" : "=f"(lo), "=f"(hi) : "l"(v));
}

// ------------------- input projection GEMM (f32x2 packed) ------------------
// C[t][col] = sum_e emb[tok[t]][e] * wih[col][e] + (bih+bhh)[col]
// Tile 128x128, 256 threads, 8x8 per thread; accumulators are f32x2 pairs
// over adjacent output columns -> half the FMA-pipe slots of scalar FFMA.
__global__ __launch_bounds__(256) void k_input_gemm(
    const int* __restrict__ tok, const float* __restrict__ emb,
    const float* __restrict__ wih, const float* __restrict__ bih,
    const float* __restrict__ bhh, int dir) {
    __shared__ float As[8][128];
    __shared__ float Bs[8][128];
    __shared__ int stok[128];

    const int t0 = blockIdx.x * 128;
    const int j0 = blockIdx.y * 128;
    const int tid = threadIdx.x;
    if (tid < 128) stok[tid] = tok[t0 + tid];
    __syncthreads();

    const int tx = tid & 15;
    const int ty = tid >> 4;
    const int r = tid >> 1;
    const int q = tid & 1;

    unsigned long long acc[8][4];   // [row i][col-pair jp]
    #pragma unroll
    for (int i = 0; i < 8; ++i)
        #pragma unroll
        for (int jp = 0; jp < 4; ++jp) acc[i][jp] = 0ull;

    for (int k0 = 0; k0 < NE; k0 += 8) {
        const int kc = k0 + q * 4;
        float4 av = make_float4(0.f, 0.f, 0.f, 0.f);
        float4 bv = make_float4(0.f, 0.f, 0.f, 0.f);
        if (kc < NE) {  // NE % 4 == 0 so a guarded float4 never straddles the edge
            av = *(const float4*)(emb + (size_t)stok[r] * NE + kc);
            bv = *(const float4*)(wih + (size_t)(j0 + r) * NE + kc);
        }
        __syncthreads();  // previous tile fully consumed
        As[q * 4 + 0][r] = av.x; As[q * 4 + 1][r] = av.y;
        As[q * 4 + 2][r] = av.z; As[q * 4 + 3][r] = av.w;
        Bs[q * 4 + 0][r] = bv.x; Bs[q * 4 + 1][r] = bv.y;
        Bs[q * 4 + 2][r] = bv.z; Bs[q * 4 + 3][r] = bv.w;
        __syncthreads();
        #pragma unroll
        for (int kk = 0; kk < 8; ++kk) {
            float a[8];
            *(float4*)&a[0] = *(const float4*)&As[kk][ty * 8];
            *(float4*)&a[4] = *(const float4*)&As[kk][ty * 8 + 4];
            ulonglong2 b01 = *(const ulonglong2*)&Bs[kk][tx * 8];      // pairs 0,1
            ulonglong2 b23 = *(const ulonglong2*)&Bs[kk][tx * 8 + 4];  // pairs 2,3
            #pragma unroll
            for (int i = 0; i < 8; ++i) {
                const unsigned long long ap = pk2(a[i]);
                ffma2(acc[i][0], ap, b01.x);
                ffma2(acc[i][1], ap, b01.y);
                ffma2(acc[i][2], ap, b23.x);
                ffma2(acc[i][3], ap, b23.y);
            }
        }
    }

    // unpack pairs -> accf[i][j]
    float accf[8][8];
    #pragma unroll
    for (int i = 0; i < 8; ++i)
        #pragma unroll
        for (int jp = 0; jp < 4; ++jp)
            upk2(acc[i][jp], accf[i][2 * jp], accf[i][2 * jp + 1]);

    // epilogue: thread covers t = t0+ty*8+i (i=0..7 -> el), col = j0+tx*8+j (-> eu)
    const int jj = j0 + tx * 8;
    float bsum[8];
    #pragma unroll
    for (int j = 0; j < 8; ++j) bsum[j] = bih[jj + j] + bhh[jj + j];

    const int tb = t0 + ty * 8;          // aligned to 8 -> el = i
    const int s = tb >> 6;
    const int cb = (tb >> 3) & 7;
    const int gate = jj >> 8;
    const int rank = (jj >> 5) & 7;
    const int eu0 = jj & 31;             // in {0,8,16,24}; j<8 stays in-range
    float* base2 = &g_G2[dir][s][cb][rank][0] + gate * 256 + eu0 * 8;

    #pragma unroll
    for (int j = 0; j < 8; ++j) {
        float4 lo = make_float4(accf[0][j] + bsum[j], accf[1][j] + bsum[j],
                                accf[2][j] + bsum[j], accf[3][j] + bsum[j]);
        float4 hi = make_float4(accf[4][j] + bsum[j], accf[5][j] + bsum[j],
                                accf[6][j] + bsum[j], accf[7][j] + bsum[j]);
        *(float4*)(base2 + j * 8) = lo;
        *(float4*)(base2 + j * 8 + 4) = hi;
    }
}

// ------------------- clustered recurrent LSTM ------------------------------
// 128 CTAs = 16 clusters of 8, 512 threads (16 warps, 4/SMSP).
// Matvec: warp=(ks,half), thread=(lg,rg) -> 4 rows x 4 lanes x 32 k, f32x2 FMA.
// Weights pitch-34 (.64 loads, bank=rg*2 -> conflict-free crossbar).
__global__ __launch_bounds__(512, 1) __cluster_dims__(CLS, 1, 1)
void k_lstm(const float* __restrict__ whh_f, const float* __restrict__ whh_b,
            const float* __restrict__ h0, const float* __restrict__ c0) {
    extern __shared__ float dsm[];
    const int tid = threadIdx.x;
    const unsigned rank = ctarank();
    const int cid = blockIdx.x >> 3;
    const int dir = cid >> 3;
    const int cb = cid & 7;
    const int bg0 = cb * LANES;
    const int u0 = rank * UPC;

    const float* __restrict__ whh = dir ? whh_b : whh_f;

    // ---- stage weight slice: W2[(ks*2+half)*4 + j][rg][kk(pitch 34)]
    for (int idx = tid; idx < ROWS * NH2; idx += 512) {
        const int row = idx >> 8;          // local gate row 0..127
        const int k = idx & 255;
        const int half = row >> 6, rp = row & 63;
        const int rg = rp >> 2, j = rp & 3;
        const int ks = k >> 5, kk = k & 31;
        const int grow = ((row >> 5) << 8) + u0 + (row & 31);
        dsm[SW_OFF + ((ks * 2 + half) * 4 + j) * WBLK + rg * WPITCH + kk] =
            whh[(size_t)grow * NH2 + k];
    }
    // ---- init h buffer 0: hT[el][k]
    for (int jdx = tid; jdx < LANES * NH2; jdx += 512) {
        const int l = jdx >> 8, k = jdx & 255;
        dsm[HB_OFF + l * HPITCH + k] = h0[(size_t)(dir * NB + bg0 + l) * NH2 + k];
    }
    // ---- phase-2 role (tid<256): (unit eu, lane el)
    const int eu = tid >> 3, el = tid & 7;
    float c = 0.0f;
    if (tid < 256)
        c = c0[(size_t)(dir * NB + bg0 + el) * NH2 + u0 + eu];

    // ---- peer hbuf base addresses
    const unsigned hb_local = smem_u32(&dsm[HB_OFF]);
    unsigned hb_peer[CLS];
    #pragma unroll
    for (int j = 0; j < CLS; ++j)
        asm("mapa.shared::cluster.u32 %0, %1, %2;"
            : "=r"(hb_peer[j]) : "r"(hb_local), "r"(j));

    // ---- matvec role
    const int w = tid >> 5;
    const int ks = w >> 1;
    const int half = w & 1;
    const int lane = tid & 31;
    const int lg = lane >> 4;       // 0..1 (4-lane group)
    const int rg = lane & 15;       // 0..15 (4-row group)
    const int wb0 = SW_OFF + (ks * 2 + half) * 4 * WBLK + rg * WPITCH;
    const int hbase = HB_OFF + lg * 4 * HPITCH + ks * 32;
    // phase-C store base: red[ks][el = lg*4 + li][row = half*64 + rg*4 .. +3]
    const int cbase = RED_OFF + ks * REDK + lg * 4 * ELP + half * 64 + rg * 4;

    // CTA-step base into g_G2
    const float* __restrict__ G2 = &g_G2[dir][0][cb][rank][0];

    __syncthreads();
    asm volatile("barrier.cluster.arrive.aligned;" ::: "memory");
    asm volatile("barrier.cluster.wait.aligned;" ::: "memory");

    int p = 0;
    for (int si = 0; si < NS; ++si) {
        const int s = dir ? (NS - 1 - si) : si;

        // phase A (tid<256): coalesced input-gate loads
        float gin0 = 0.f, gin1 = 0.f, gin2 = 0.f, gin3 = 0.f;
        if (tid < 256) {
            const float* Gp = G2 + (size_t)s * (8 * 8 * 1024) + tid;
            gin0 = Gp[0];
            gin1 = Gp[256];
            gin2 = Gp[512];
            gin3 = Gp[768];
        }

        // phase B: matvec, 4 rows (j) x 4 lanes (li) x 32 k
        unsigned long long accp[16];
        #pragma unroll
        for (int i = 0; i < 16; ++i) accp[i] = 0ull;

        const float* Hb = &dsm[hbase + p * HBUF];
        #pragma unroll
        for (int kq = 0; kq < 8; ++kq) {
            ulonglong2 hq[4];
            #pragma unroll
            for (int li = 0; li < 4; ++li)
                hq[li] = *(const ulonglong2*)(Hb + li * HPITCH + kq * 4);
            #pragma unroll
            for (int j = 0; j < 4; ++j) {
                const unsigned long long wlo =
                    *(const unsigned long long*)&dsm[wb0 + j * WBLK + kq * 4];
                const unsigned long long whi =
                    *(const unsigned long long*)&dsm[wb0 + j * WBLK + kq * 4 + 2];
                #pragma unroll
                for (int li = 0; li < 4; ++li) {
                    ffma2(accp[j * 4 + li], wlo, hq[li].x);
                    ffma2(accp[j * 4 + li], whi, hq[li].y);
                }
            }
        }

        // phase C: stage partials  red[ks][el][row], one float4 (4 rows) per el
        #pragma unroll
        for (int li = 0; li < 4; ++li) {
            float4 v = make_float4(hadd2(accp[0 * 4 + li]), hadd2(accp[1 * 4 + li]),
                                   hadd2(accp[2 * 4 + li]), hadd2(accp[3 * 4 + li]));
            *(float4*)&dsm[cbase + li * ELP] = v;  // 16B-aligned (ELP=132)
        }
        __syncthreads();

        // phase D (tid<256): reduce 8 k-slices + LSTM cell + h broadcast
        if (tid < 256) {
            float g0 = gin0, g1 = gin1, g2 = gin2, g3 = gin3;
            const float* rb = &dsm[RED_OFF + el * ELP];
            #pragma unroll
            for (int kk = 0; kk < 8; ++kk) {
                const float* rk = rb + kk * REDK;
                g0 += rk[eu];
                g1 += rk[32 + eu];
                g2 += rk[64 + eu];
                g3 += rk[96 + eu];
            }
            const float iv = sigf(g0), fv = sigf(g1);
            const float gv = tanhf(g2), ov = sigf(g3);
            c = fv * c + iv * gv;
            const float h = ov * tanhf(c);

            const unsigned off = (((p ^ 1) * HBUF) + el * HPITCH + u0 + eu) * 4u;
            #pragma unroll
            for (int j = 0; j < CLS; ++j)
                asm volatile("st.shared::cluster.f32 [%0], %1;"
                             :: "r"(hb_peer[j] + off), "f"(h) : "memory");
        }
        __syncthreads();   // own h-stores visible locally for phase E

        // phase E (tid<256): coalesced g_lstm writeback from local buffer p^1
        if (tid < 256) {
            const int el2 = tid >> 5, ul = tid & 31;
            const float hv = dsm[HB_OFF + (p ^ 1) * HBUF + el2 * HPITCH + u0 + ul];
            g_lstm[s * NB + bg0 + el2][dir * NH2 + u0 + ul] = hv;
        }

        // phase F: cluster barrier (release peer stores / acquire for next read)
        asm volatile("barrier.cluster.arrive.aligned;" ::: "memory");
        asm volatile("barrier.cluster.wait.aligned;" ::: "memory");
        p ^= 1;
    }
}

// ------------------- emission features: lstm_out @ W_out^T + b_out ---------
__global__ __launch_bounds__(256) void k_feats(const float* __restrict__ Wout,
                                               const float* __restrict__ bout) {
    __shared__ float sW[NT][2 * NH2];
    const int tid = threadIdx.x;
    for (int i = tid; i < NT * 2 * NH2; i += 256) sW[i / (2 * NH2)][i % (2 * NH2)] = Wout[i];
    __syncthreads();

    const int warp = tid >> 5, lane = tid & 31;
    const int n = blockIdx.x * 8 + warp;
    const float4* row = (const float4*)&g_lstm[n][0];

    float pAcc[NT];
    #pragma unroll
    for (int t = 0; t < NT; ++t) pAcc[t] = 0.0f;
    for (int q = lane; q < 128; q += 32) {
        const float4 v = row[q];
        #pragma unroll
        for (int t = 0; t < NT; ++t) {
            const float4 wv = ((const float4*)&sW[t][0])[q];
            pAcc[t] += v.x * wv.x + v.y * wv.y + v.z * wv.z + v.w * wv.w;
        }
    }
    #pragma unroll
    for (int off = 16; off; off >>= 1)
        #pragma unroll
        for (int t = 0; t < NT; ++t)
            pAcc[t] += __shfl_down_sync(0xffffffffu, pAcc[t], off);
    if (lane == 0) {
        #pragma unroll
        for (int t = 0; t < NT; ++t) g_feats[n][t] = pAcc[t] + bout[t];
    }
}

// ------------------- Viterbi decode (1 warp per batch element) -------------
__global__ void k_viterbi(const float* __restrict__ trans, float* __restrict__ out) {
    const int b = blockIdx.x;
    const int lane = threadIdx.x;
    __shared__ float st[NT * NT];
    __shared__ unsigned char bp[NS][NT];
    for (int i = lane; i < NT * NT; i += 32) st[i] = trans[i];
    __syncwarp();

    float fv = (lane == IDX_START) ? 0.0f : -10000.0f;
    for (int s = 0; s < NS; ++s) {
        float best = -3.4e38f;
        int barg = 0;
        const float cur = fv;
        #pragma unroll
        for (int p = 0; p < NT; ++p) {
            const float fp = __shfl_sync(0xffffffffu, cur, p);
            if (lane < NT) {
                const float v = fp + st[lane * NT + p];
                if (v > best) { best = v; barg = p; }
            }
        }
        float feat = 0.0f;
        if (lane < NT) feat = g_feats[b * NS + s][lane];
        fv = best + feat;
        if (lane < NT) bp[s][lane] = (unsigned char)barg;
        __syncwarp();
    }
    float m = (lane < NT) ? (fv + st[IDX_STOP * NT + lane]) : -3.4e38f;
    int mi = lane;
    #pragma unroll
    for (int off = 16; off; off >>= 1) {
        const float om = __shfl_down_sync(0xffffffffu, m, off);
        const int oi = __shfl_down_sync(0xffffffffu, mi, off);
        if (om > m || (om == m && oi < mi)) { m = om; mi = oi; }
    }
    if (lane == 0) {
        out[b] = m;
        int best = mi;
        for (int s = NS - 1; s >= 0; --s) {
            out[NB + b * NS + s] = (float)best;
            best = bp[s][best];
        }
    }
}

// ------------------- launcher ----------------------------------------------
extern "C" void kernel_launch(void* const* d_in, const int* in_sizes, int n_in,
                              void* d_out, int out_size) {
    const int*   sent  = (const int*)d_in[0];
    const float* emb   = (const float*)d_in[1];
    const float* wih_f = (const float*)d_in[2];
    const float* whh_f = (const float*)d_in[3];
    const float* bih_f = (const float*)d_in[4];
    const float* bhh_f = (const float*)d_in[5];
    const float* wih_b = (const float*)d_in[6];
    const float* whh_b = (const float*)d_in[7];
    const float* bih_b = (const float*)d_in[8];
    const float* bhh_b = (const float*)d_in[9];
    const float* Wout  = (const float*)d_in[10];
    const float* bout  = (const float*)d_in[11];

    const float *trans, *h0, *c0;
    if (n_in > 12 && in_sizes[12] == NT * NT) {
        trans = (const float*)d_in[12];
        h0    = (const float*)d_in[13];
        c0    = (const float*)d_in[14];
    } else {
        h0    = (const float*)d_in[12];
        c0    = (const float*)d_in[13];
        trans = (const float*)d_in[14];
    }

    static int smem_set = 0;
    const int lstm_smem = DSM_FLOATS * (int)sizeof(float);  // ~185.5 KB
    if (!smem_set) {
        cudaFuncSetAttribute(k_lstm, cudaFuncAttributeMaxDynamicSharedMemorySize,
                             lstm_smem);
        smem_set = 1;
    }

    {
        dim3 gg(NM / 128, NG / 128);
        k_input_gemm<<<gg, 256>>>(sent, emb, wih_f, bih_f, bhh_f, 0);
        k_input_gemm<<<gg, 256>>>(sent, emb, wih_b, bih_b, bhh_b, 1);
    }
    k_lstm<<<128, 512, lstm_smem>>>(whh_f, whh_b, h0, c0);
    k_feats<<<NM / 8, 256>>>(Wout, bout);
    k_viterbi<<<NB, 32>>>(trans, (float*)d_out);
}